// round 8
// baseline (speedup 1.0000x reference)
#include <cuda_runtime.h>

// PTDNet-GCN fused pipeline, round 7:
//  - GEMM: tf32 mma m16n8k8, 3xTF32 compensation; warp-per-16-rows (m16n32),
//    software-prefetched A and W loads for high MLP, ~60 regs for occupancy.
//  - Everything else as round 6.

#define N_NODES 100000
#define N_EDGES 1600000
#define IN_DIM  512
#define H0      32
#define H1      8
#define ZETA    1.01f
#define NB_SCAN 98            // ceil(100000/1024)
#define N_WARPS_GEMM 6250     // 100000 / 16

// ---------------- scratch (static device memory) ----------------------------
__device__ float  g_xw[N_NODES * H0];     // dinv0[row] * (x @ W0)
__device__ float  g_hw[N_NODES * H1];     // h @ W1
__device__ float  g_hws[N_NODES * H1];    // dinv1[row] * hw
__device__ int    g_cnt[N_NODES];
__device__ int    g_off[N_NODES];         // bucket start (non-monotone partition)
__device__ int    g_cursor[N_NODES];
__device__ int    g_total;
__device__ int    g_src[N_EDGES];
__device__ float  g_mw[N_EDGES];
__device__ float  g_dinv0[N_NODES];
__device__ float  g_dinv1[N_NODES];
__device__ float  g_u[N_NODES];
__device__ float  g_v[N_NODES];
__device__ float  g_att_a[H0];
__device__ float  g_att_b[H0];
__device__ float  g_cst;
// W0 fragments: [64 k-steps][4 n-tiles][32 lanes] -> (b0_hi, b1_hi, b0_lo, b1_lo)
__device__ float4 g_wf[64 * 4 * 32];

// ---------------- helpers ---------------------------------------------------
__device__ __forceinline__ float wred(float x) {
    x += __shfl_xor_sync(0xffffffffu, x, 16);
    x += __shfl_xor_sync(0xffffffffu, x, 8);
    x += __shfl_xor_sync(0xffffffffu, x, 4);
    x += __shfl_xor_sync(0xffffffffu, x, 2);
    x += __shfl_xor_sync(0xffffffffu, x, 1);
    return x;
}

__device__ __forceinline__ unsigned f2tf(float x) {
    unsigned u;
    asm("cvt.rna.tf32.f32 %0, %1;" : "=r"(u) : "f"(x));
    return u;
}

__device__ __forceinline__ void mma_tf32(float* d, const unsigned* a,
                                         unsigned b0, unsigned b1) {
    asm("mma.sync.aligned.m16n8k8.row.col.f32.tf32.tf32.f32 "
        "{%0,%1,%2,%3}, {%4,%5,%6,%7}, {%8,%9}, {%0,%1,%2,%3};"
        : "+f"(d[0]), "+f"(d[1]), "+f"(d[2]), "+f"(d[3])
        : "r"(a[0]), "r"(a[1]), "r"(a[2]), "r"(a[3]), "r"(b0), "r"(b1));
}

// ---------------- 1) zero counters + attn prep + W fragment swizzle ----------
__global__ __launch_bounds__(1024) void zero_prep(
        const float* __restrict__ W0,
        const float* __restrict__ Wnb, const float* __restrict__ bnb,
        const float* __restrict__ Wself, const float* __restrict__ bself,
        const float* __restrict__ Watt, const float* __restrict__ batt) {
    int i = blockIdx.x * 1024 + threadIdx.x;
    if (i < N_NODES) g_cnt[i] = 0;
    if (blockIdx.x == 0) {
        if (threadIdx.x == 0) g_total = 0;
        if (threadIdx.x < 32) {
            int j = threadIdx.x;
            float a = 0.f, b = 0.f;
#pragma unroll
            for (int q = 0; q < 8; ++q) {
                a += Wnb[j * 8 + q] * Watt[q];
                b += Wself[j * 8 + q] * Watt[8 + q];
            }
            g_att_a[j] = a;
            g_att_b[j] = b;
            if (j == 0) {
                float c = batt[0];
#pragma unroll
                for (int q = 0; q < 8; ++q)
                    c += bnb[q] * Watt[q] + bself[q] * Watt[8 + q];
                g_cst = c;
            }
        }
    } else if (blockIdx.x <= 8) {
        // W fragment swizzle: idx over 64*4*32 = 8192 entries
        int idx = (blockIdx.x - 1) * 1024 + threadIdx.x;
        int s = idx >> 7;            // k-step
        int t = (idx >> 5) & 3;      // n-tile
        int lane = idx & 31;
        int tig = lane & 3, gid = lane >> 2;
        float b0 = W0[(8 * s + tig) * 32 + 8 * t + gid];
        float b1 = W0[(8 * s + tig + 4) * 32 + 8 * t + gid];
        unsigned b0h = f2tf(b0), b1h = f2tf(b1);
        float b0hf = __uint_as_float(b0h), b1hf = __uint_as_float(b1h);
        unsigned b0l = f2tf(b0 - b0hf), b1l = f2tf(b1 - b1hf);
        g_wf[idx] = make_float4(b0hf, b1hf,
                                __uint_as_float(b0l), __uint_as_float(b1l));
    }
}

// ---------------- 2) in-degree count (4 edges / thread, int4) ----------------
__global__ void count_kernel(const int* __restrict__ eidx) {
    int t = blockIdx.x * blockDim.x + threadIdx.x;
    if (t >= N_EDGES / 4) return;
    int4 c = *(const int4*)(eidx + N_EDGES + t * 4);
    atomicAdd(&g_cnt[c.x], 1);
    atomicAdd(&g_cnt[c.y], 1);
    atomicAdd(&g_cnt[c.z], 1);
    atomicAdd(&g_cnt[c.w], 1);
}

// ---------------- 3) fused scan: block-local scan + atomic base --------------
__global__ __launch_bounds__(1024) void scan_fused() {
    __shared__ int sm[1024];
    __shared__ int sbase;
    int tid = threadIdx.x;
    int i = blockIdx.x * 1024 + tid;
    int v = (i < N_NODES) ? g_cnt[i] : 0;
    sm[tid] = v;
    __syncthreads();
    for (int o = 1; o < 1024; o <<= 1) {
        int t = (tid >= o) ? sm[tid - o] : 0;
        __syncthreads();
        sm[tid] += t;
        __syncthreads();
    }
    if (tid == 1023) sbase = atomicAdd(&g_total, sm[1023]);
    __syncthreads();
    if (i < N_NODES) {
        int o = sm[tid] - v + sbase;
        g_off[i] = o;
        g_cursor[i] = o;
        g_dinv0[i] = rsqrtf((float)v + 1.0f);
    }
}

// ---------------- 4) xw = dinv0 * (x @ W0)  (tf32 mma, 3xTF32) ---------------
// Warp per 16 rows (m16n32). Prefetched A + W loads for MLP; ~60 regs.
__global__ __launch_bounds__(256) void gemm_xw(const float* __restrict__ x) {
    int wid = (blockIdx.x * blockDim.x + threadIdx.x) >> 5;
    if (wid >= N_WARPS_GEMM) return;
    int lane = threadIdx.x & 31;
    int gid = lane >> 2, tig = lane & 3;
    int row0 = wid * 16;

    const float* pA = x + (size_t)(row0 + gid) * IN_DIM;
    const float* pB = pA + 8 * IN_DIM;

    float acc[4][4];
#pragma unroll
    for (int t = 0; t < 4; ++t)
#pragma unroll
        for (int r = 0; r < 4; ++r) acc[t][r] = 0.f;

    // prefetch s = 0
    float a0 = __ldg(pA + tig);
    float a1 = __ldg(pB + tig);
    float a2 = __ldg(pA + tig + 4);
    float a3 = __ldg(pB + tig + 4);

    for (int s = 0; s < 64; ++s) {
        // W fragments for this step: 4 x LDG.128, issued up front
        const float4* wp = g_wf + (s * 4) * 32 + lane;
        float4 w0 = __ldg(wp);
        float4 w1 = __ldg(wp + 32);
        float4 w2 = __ldg(wp + 64);
        float4 w3 = __ldg(wp + 96);

        // prefetch A for s+1
        float n0, n1, n2, n3;
        if (s < 63) {
            int k1 = (s + 1) * 8 + tig;
            n0 = __ldg(pA + k1);
            n1 = __ldg(pB + k1);
            n2 = __ldg(pA + k1 + 4);
            n3 = __ldg(pB + k1 + 4);
        } else {
            n0 = n1 = n2 = n3 = 0.f;
        }

        unsigned ah[4], al[4];
        ah[0] = f2tf(a0); al[0] = f2tf(a0 - __uint_as_float(ah[0]));
        ah[1] = f2tf(a1); al[1] = f2tf(a1 - __uint_as_float(ah[1]));
        ah[2] = f2tf(a2); al[2] = f2tf(a2 - __uint_as_float(ah[2]));
        ah[3] = f2tf(a3); al[3] = f2tf(a3 - __uint_as_float(ah[3]));

        {
            unsigned bh0 = __float_as_uint(w0.x), bh1 = __float_as_uint(w0.y);
            unsigned bl0 = __float_as_uint(w0.z), bl1 = __float_as_uint(w0.w);
            mma_tf32(acc[0], ah, bh0, bh1);
            mma_tf32(acc[0], al, bh0, bh1);
            mma_tf32(acc[0], ah, bl0, bl1);
        }
        {
            unsigned bh0 = __float_as_uint(w1.x), bh1 = __float_as_uint(w1.y);
            unsigned bl0 = __float_as_uint(w1.z), bl1 = __float_as_uint(w1.w);
            mma_tf32(acc[1], ah, bh0, bh1);
            mma_tf32(acc[1], al, bh0, bh1);
            mma_tf32(acc[1], ah, bl0, bl1);
        }
        {
            unsigned bh0 = __float_as_uint(w2.x), bh1 = __float_as_uint(w2.y);
            unsigned bl0 = __float_as_uint(w2.z), bl1 = __float_as_uint(w2.w);
            mma_tf32(acc[2], ah, bh0, bh1);
            mma_tf32(acc[2], al, bh0, bh1);
            mma_tf32(acc[2], ah, bl0, bl1);
        }
        {
            unsigned bh0 = __float_as_uint(w3.x), bh1 = __float_as_uint(w3.y);
            unsigned bl0 = __float_as_uint(w3.z), bl1 = __float_as_uint(w3.w);
            mma_tf32(acc[3], ah, bh0, bh1);
            mma_tf32(acc[3], al, bh0, bh1);
            mma_tf32(acc[3], ah, bl0, bl1);
        }

        a0 = n0; a1 = n1; a2 = n2; a3 = n3;
    }

    // epilogue: scale rows by rsqrt(indeg+1), store float2 pairs
    int rA = row0 + gid;
    int rB = rA + 8;
    float dA = rsqrtf((float)g_cnt[rA] + 1.f);
    float dB = rsqrtf((float)g_cnt[rB] + 1.f);
#pragma unroll
    for (int t = 0; t < 4; ++t) {
        int col = t * 8 + tig * 2;
        *(float2*)(g_xw + rA * 32 + col) =
            make_float2(acc[t][0] * dA, acc[t][1] * dA);
        *(float2*)(g_xw + rB * 32 + col) =
            make_float2(acc[t][2] * dB, acc[t][3] * dB);
    }
}

// ---------------- 5) CSR fill (2 edges / thread, batched loads) --------------
__global__ void fill_kernel(const int* __restrict__ eidx) {
    int t = blockIdx.x * blockDim.x + threadIdx.x;
    if (t >= N_EDGES / 2) return;
    int2 r = *(const int2*)(eidx + t * 2);
    int2 c = *(const int2*)(eidx + N_EDGES + t * 2);
    int pos0 = atomicAdd(&g_cursor[c.x], 1);
    int pos1 = atomicAdd(&g_cursor[c.y], 1);
    g_src[pos0] = r.x;
    g_src[pos1] = r.y;
}

// ---------------- 6) conv0 + fused (hw, u, v) --------------------------------
__global__ __launch_bounds__(256) void conv0_kernel(const float* __restrict__ b0,
                                                    const float* __restrict__ W1) {
    __shared__ float hsm[8][32];
    int warp = (blockIdx.x * blockDim.x + threadIdx.x) >> 5;
    int lane = threadIdx.x & 31;
    int w = threadIdx.x >> 5;
    if (warp >= N_NODES) return;
    int node = warp;
    int s = g_off[node];
    int e = s + g_cnt[node];
    int g = lane >> 3;
    int f4 = (lane & 7) * 4;

    float4 acc;
    if (g == 0) acc = *(const float4*)(g_xw + node * 32 + f4);  // self (pre-scaled)
    else        acc = make_float4(0.f, 0.f, 0.f, 0.f);

    for (int p0 = s; p0 < e; p0 += 8) {
        int pA = p0 + g;
        int pB = p0 + 4 + g;
        int rA = (pA < e) ? g_src[pA] : -1;
        int rB = (pB < e) ? g_src[pB] : -1;
        if (rA >= 0) {
            float4 xv = *(const float4*)(g_xw + rA * 32 + f4);
            acc.x += xv.x; acc.y += xv.y; acc.z += xv.z; acc.w += xv.w;
        }
        if (rB >= 0) {
            float4 xv = *(const float4*)(g_xw + rB * 32 + f4);
            acc.x += xv.x; acc.y += xv.y; acc.z += xv.z; acc.w += xv.w;
        }
    }
    acc.x += __shfl_xor_sync(0xffffffffu, acc.x, 8);
    acc.y += __shfl_xor_sync(0xffffffffu, acc.y, 8);
    acc.z += __shfl_xor_sync(0xffffffffu, acc.z, 8);
    acc.w += __shfl_xor_sync(0xffffffffu, acc.w, 8);
    acc.x += __shfl_xor_sync(0xffffffffu, acc.x, 16);
    acc.y += __shfl_xor_sync(0xffffffffu, acc.y, 16);
    acc.z += __shfl_xor_sync(0xffffffffu, acc.z, 16);
    acc.w += __shfl_xor_sync(0xffffffffu, acc.w, 16);

    float dc = g_dinv0[node];
    if (g == 0) {
        hsm[w][f4 + 0] = dc * acc.x + __ldg(b0 + f4 + 0);
        hsm[w][f4 + 1] = dc * acc.y + __ldg(b0 + f4 + 1);
        hsm[w][f4 + 2] = dc * acc.z + __ldg(b0 + f4 + 2);
        hsm[w][f4 + 3] = dc * acc.w + __ldg(b0 + f4 + 3);
    }
    __syncwarp();

    float q = 0.f;
    if (lane < 8) {
#pragma unroll
        for (int j = 0; j < 32; ++j) q += hsm[w][j] * __ldg(W1 + j * 8 + lane);
        g_hw[node * 8 + lane] = q;
    } else if (lane == 8) {
#pragma unroll
        for (int j = 0; j < 32; ++j) q += hsm[w][j] * g_att_a[j];
        g_u[node] = q;
    } else if (lane == 9) {
#pragma unroll
        for (int j = 0; j < 32; ++j) q += hsm[w][j] * g_att_b[j];
        g_v[node] = q;
    }
}

// ---------------- 7) attention weights + dinv1 + hws -------------------------
__global__ __launch_bounds__(256) void attn_kernel() {
    int warp = (blockIdx.x * blockDim.x + threadIdx.x) >> 5;
    int lane = threadIdx.x & 31;
    if (warp >= N_NODES) return;
    int node = warp;
    float vc = g_v[node] + g_cst;
    int s = g_off[node];
    int e = s + g_cnt[node];
    float sum = 0.f;
    for (int p0 = s; p0 < e; p0 += 32) {
        int p = p0 + lane;
        float mw = 0.f;
        if (p < e) {
            int r = g_src[p];
            float wgt = fmaxf(g_u[r] + vc, 0.f);
            float m = fminf(ZETA / (1.f + __expf(-wgt)), 1.f);
            mw = m * wgt;
            g_mw[p] = mw;
        }
        sum += mw;
    }
    sum = wred(sum);
    float d1 = rsqrtf(sum + 1.0f);
    if (lane == 0) g_dinv1[node] = d1;
    if (lane < 8) g_hws[node * 8 + lane] = d1 * g_hw[node * 8 + lane];
}

// ---------------- 8) conv1 ---------------------------------------------------
__global__ __launch_bounds__(256) void conv1_kernel(const float* __restrict__ b1,
                                                    float* __restrict__ out) {
    int warp = (blockIdx.x * blockDim.x + threadIdx.x) >> 5;
    int lane = threadIdx.x & 31;
    if (warp >= N_NODES) return;
    int node = warp;
    int s = g_off[node];
    int e = s + g_cnt[node];
    int g = lane >> 3;
    int f = lane & 7;

    float acc = (g == 0) ? g_hws[node * 8 + f] : 0.f;  // self term

    for (int p0 = s; p0 < e; p0 += 8) {
        int pA = p0 + g;
        int pB = p0 + 4 + g;
        int rA = (pA < e) ? g_src[pA] : -1;
        int rB = (pB < e) ? g_src[pB] : -1;
        float cA = (pA < e) ? g_mw[pA] : 0.f;
        float cB = (pB < e) ? g_mw[pB] : 0.f;
        if (rA >= 0) acc += cA * g_hws[rA * 8 + f];
        if (rB >= 0) acc += cB * g_hws[rB * 8 + f];
    }
    acc += __shfl_xor_sync(0xffffffffu, acc, 8);
    acc += __shfl_xor_sync(0xffffffffu, acc, 16);

    if (lane < 8)
        out[node * 8 + lane] = g_dinv1[node] * acc + __ldg(b1 + lane);
}

// ---------------- launch -----------------------------------------------------
extern "C" void kernel_launch(void* const* d_in, const int* in_sizes, int n_in,
                              void* d_out, int out_size) {
    const float* x     = (const float*)d_in[0];
    const int*   eidx  = (const int*)  d_in[1];
    const float* W0    = (const float*)d_in[2];
    const float* b0    = (const float*)d_in[3];
    const float* W1    = (const float*)d_in[4];
    const float* b1    = (const float*)d_in[5];
    const float* Wnb   = (const float*)d_in[6];
    const float* bnb   = (const float*)d_in[7];
    const float* Wself = (const float*)d_in[8];
    const float* bself = (const float*)d_in[9];
    const float* Watt  = (const float*)d_in[10];
    const float* batt  = (const float*)d_in[11];
    float* out = (float*)d_out;

    zero_prep<<<NB_SCAN, 1024>>>(W0, Wnb, bnb, Wself, bself, Watt, batt);     // 0
    count_kernel<<<(N_EDGES / 4 + 255) / 256, 256>>>(eidx);                   // 1
    scan_fused<<<NB_SCAN, 1024>>>();                                          // 2
    gemm_xw<<<(N_WARPS_GEMM * 32 + 255) / 256, 256>>>(x);                     // 3 (profiled)
    fill_kernel<<<(N_EDGES / 2 + 255) / 256, 256>>>(eidx);                    // 4
    conv0_kernel<<<(N_NODES * 32 + 255) / 256, 256>>>(b0, W1);                // 5
    attn_kernel<<<(N_NODES * 32 + 255) / 256, 256>>>();                       // 6
    conv1_kernel<<<(N_NODES * 32 + 255) / 256, 256>>>(b1, out);               // 7
}

// round 10
// speedup vs baseline: 1.0242x; 1.0242x over previous
#include <cuda_runtime.h>

// PTDNet-GCN fused pipeline, round 9:
//  - GEMM: cp.async double-buffered smem staging (k-chunks of 16), warp-per-32-rows
//    m16n8k8 tf32 with 3xTF32 compensation. Row stride 20 floats (80 B): 16B-aligned
//    for cp.async AND conflict-free for the fragment read pattern.
//  - Everything else as round 6 (best known).

#define N_NODES 100000
#define N_EDGES 1600000
#define IN_DIM  512
#define H0      32
#define H1      8
#define ZETA    1.01f
#define NB_SCAN 98            // ceil(100000/1024)

// ---------------- scratch (static device memory) ----------------------------
__device__ float  g_xw[N_NODES * H0];     // dinv0[row] * (x @ W0)
__device__ float  g_hw[N_NODES * H1];     // h @ W1
__device__ float  g_hws[N_NODES * H1];    // dinv1[row] * hw
__device__ int    g_cnt[N_NODES];
__device__ int    g_off[N_NODES];         // bucket start (non-monotone partition)
__device__ int    g_cursor[N_NODES];
__device__ int    g_total;
__device__ int    g_src[N_EDGES];
__device__ float  g_mw[N_EDGES];
__device__ float  g_dinv0[N_NODES];
__device__ float  g_dinv1[N_NODES];
__device__ float  g_u[N_NODES];
__device__ float  g_v[N_NODES];
__device__ float  g_att_a[H0];
__device__ float  g_att_b[H0];
__device__ float  g_cst;
// W0 fragments: [64 k-steps][4 n-tiles][32 lanes] -> (b0_hi, b1_hi, b0_lo, b1_lo)
__device__ float4 g_wf[64 * 4 * 32];

// ---------------- helpers ---------------------------------------------------
__device__ __forceinline__ float wred(float x) {
    x += __shfl_xor_sync(0xffffffffu, x, 16);
    x += __shfl_xor_sync(0xffffffffu, x, 8);
    x += __shfl_xor_sync(0xffffffffu, x, 4);
    x += __shfl_xor_sync(0xffffffffu, x, 2);
    x += __shfl_xor_sync(0xffffffffu, x, 1);
    return x;
}

__device__ __forceinline__ unsigned f2tf(float x) {
    unsigned u;
    asm("cvt.rna.tf32.f32 %0, %1;" : "=r"(u) : "f"(x));
    return u;
}

__device__ __forceinline__ void mma_tf32(float* d, const unsigned* a,
                                         unsigned b0, unsigned b1) {
    asm("mma.sync.aligned.m16n8k8.row.col.f32.tf32.tf32.f32 "
        "{%0,%1,%2,%3}, {%4,%5,%6,%7}, {%8,%9}, {%0,%1,%2,%3};"
        : "+f"(d[0]), "+f"(d[1]), "+f"(d[2]), "+f"(d[3])
        : "r"(a[0]), "r"(a[1]), "r"(a[2]), "r"(a[3]), "r"(b0), "r"(b1));
}

// ---------------- 1) zero counters + attn prep + W fragment swizzle ----------
__global__ __launch_bounds__(1024) void zero_prep(
        const float* __restrict__ W0,
        const float* __restrict__ Wnb, const float* __restrict__ bnb,
        const float* __restrict__ Wself, const float* __restrict__ bself,
        const float* __restrict__ Watt, const float* __restrict__ batt) {
    int i = blockIdx.x * 1024 + threadIdx.x;
    if (i < N_NODES) g_cnt[i] = 0;
    if (blockIdx.x == 0) {
        if (threadIdx.x == 0) g_total = 0;
        if (threadIdx.x < 32) {
            int j = threadIdx.x;
            float a = 0.f, b = 0.f;
#pragma unroll
            for (int q = 0; q < 8; ++q) {
                a += Wnb[j * 8 + q] * Watt[q];
                b += Wself[j * 8 + q] * Watt[8 + q];
            }
            g_att_a[j] = a;
            g_att_b[j] = b;
            if (j == 0) {
                float c = batt[0];
#pragma unroll
                for (int q = 0; q < 8; ++q)
                    c += bnb[q] * Watt[q] + bself[q] * Watt[8 + q];
                g_cst = c;
            }
        }
    } else if (blockIdx.x <= 8) {
        // W fragment swizzle: idx over 64*4*32 = 8192 entries
        int idx = (blockIdx.x - 1) * 1024 + threadIdx.x;
        int s = idx >> 7;            // k-step
        int t = (idx >> 5) & 3;      // n-tile
        int lane = idx & 31;
        int tig = lane & 3, gid = lane >> 2;
        float b0 = W0[(8 * s + tig) * 32 + 8 * t + gid];
        float b1 = W0[(8 * s + tig + 4) * 32 + 8 * t + gid];
        unsigned b0h = f2tf(b0), b1h = f2tf(b1);
        float b0hf = __uint_as_float(b0h), b1hf = __uint_as_float(b1h);
        unsigned b0l = f2tf(b0 - b0hf), b1l = f2tf(b1 - b1hf);
        g_wf[idx] = make_float4(b0hf, b1hf,
                                __uint_as_float(b0l), __uint_as_float(b1l));
    }
}

// ---------------- 2) in-degree count (4 edges / thread, int4) ----------------
__global__ void count_kernel(const int* __restrict__ eidx) {
    int t = blockIdx.x * blockDim.x + threadIdx.x;
    if (t >= N_EDGES / 4) return;
    int4 c = *(const int4*)(eidx + N_EDGES + t * 4);
    atomicAdd(&g_cnt[c.x], 1);
    atomicAdd(&g_cnt[c.y], 1);
    atomicAdd(&g_cnt[c.z], 1);
    atomicAdd(&g_cnt[c.w], 1);
}

// ---------------- 3) fused scan: block-local scan + atomic base --------------
__global__ __launch_bounds__(1024) void scan_fused() {
    __shared__ int sm[1024];
    __shared__ int sbase;
    int tid = threadIdx.x;
    int i = blockIdx.x * 1024 + tid;
    int v = (i < N_NODES) ? g_cnt[i] : 0;
    sm[tid] = v;
    __syncthreads();
    for (int o = 1; o < 1024; o <<= 1) {
        int t = (tid >= o) ? sm[tid - o] : 0;
        __syncthreads();
        sm[tid] += t;
        __syncthreads();
    }
    if (tid == 1023) sbase = atomicAdd(&g_total, sm[1023]);
    __syncthreads();
    if (i < N_NODES) {
        int o = sm[tid] - v + sbase;
        g_off[i] = o;
        g_cursor[i] = o;
        g_dinv0[i] = rsqrtf((float)v + 1.0f);
    }
}

// ---------------- 4) xw = dinv0 * (x @ W0)  (cp.async + tf32 mma) ------------
// 128 threads / 128 rows per block; warp = 32 rows (2 m-tiles x 4 n-tiles).
// Double-buffered k-chunks of 16 staged via cp.async.
// Row stride 20 floats = 80 B: every float4 slot 16B-aligned (cp.async req),
// and bank pattern (gid*20+tig)%32 is conflict-free across the warp.
#define KCHUNK 16
#define KPAD   20
#define NCHUNK (IN_DIM / KCHUNK)   // 32
__global__ __launch_bounds__(128) void gemm_xw(const float* __restrict__ x) {
    __shared__ float xs[2][128][KPAD];
    int tid = threadIdx.x;
    int lane = tid & 31;
    int warp = tid >> 5;            // 0..3
    int row0 = blockIdx.x * 128;
    int gid = lane >> 2, tig = lane & 3;
    int wrow = warp * 32;

    float acc[2][4][4];
#pragma unroll
    for (int m = 0; m < 2; ++m)
#pragma unroll
        for (int t = 0; t < 4; ++t)
#pragma unroll
            for (int r = 0; r < 4; ++r) acc[m][t][r] = 0.f;

    // issue chunk c into buffer buf
    auto load_chunk = [&](int c, int buf) {
        int k0 = c * KCHUNK;
#pragma unroll
        for (int it = 0; it < 4; ++it) {
            int idx = tid + it * 128;        // 0..511 float4 slots
            int rr = idx >> 2;               // 0..127
            int cc = (idx & 3) * 4;          // 0,4,8,12
            int grow = row0 + rr;
            if (grow >= N_NODES) grow = N_NODES - 1;   // clamp (stores guarded)
            const float* src = x + (size_t)grow * IN_DIM + k0 + cc;
            unsigned dst = (unsigned)__cvta_generic_to_shared(&xs[buf][rr][cc]);
            asm volatile("cp.async.ca.shared.global [%0], [%1], 16;"
                         :: "r"(dst), "l"(src));
        }
        asm volatile("cp.async.commit_group;");
    };

    load_chunk(0, 0);

    for (int c = 0; c < NCHUNK; ++c) {
        if (c + 1 < NCHUNK) {
            load_chunk(c + 1, (c + 1) & 1);
            asm volatile("cp.async.wait_group 1;");
        } else {
            asm volatile("cp.async.wait_group 0;");
        }
        __syncthreads();
        int buf = c & 1;

#pragma unroll
        for (int ks = 0; ks < 2; ++ks) {
            int s = c * 2 + ks;              // global k-step 0..63
            int kk = ks * 8 + tig;
            float a[2][4];
            a[0][0] = xs[buf][wrow + gid     ][kk];
            a[0][1] = xs[buf][wrow + gid + 8 ][kk];
            a[0][2] = xs[buf][wrow + gid     ][kk + 4];
            a[0][3] = xs[buf][wrow + gid + 8 ][kk + 4];
            a[1][0] = xs[buf][wrow + gid + 16][kk];
            a[1][1] = xs[buf][wrow + gid + 24][kk];
            a[1][2] = xs[buf][wrow + gid + 16][kk + 4];
            a[1][3] = xs[buf][wrow + gid + 24][kk + 4];

            unsigned ah[2][4], al[2][4];
#pragma unroll
            for (int m = 0; m < 2; ++m)
#pragma unroll
                for (int j = 0; j < 4; ++j) {
                    unsigned h = f2tf(a[m][j]);
                    ah[m][j] = h;
                    al[m][j] = f2tf(a[m][j] - __uint_as_float(h));
                }

#pragma unroll
            for (int t = 0; t < 4; ++t) {
                float4 w = __ldg(&g_wf[(s * 4 + t) * 32 + lane]);
                unsigned bh0 = __float_as_uint(w.x), bh1 = __float_as_uint(w.y);
                unsigned bl0 = __float_as_uint(w.z), bl1 = __float_as_uint(w.w);
#pragma unroll
                for (int m = 0; m < 2; ++m) {
                    mma_tf32(acc[m][t], ah[m], bh0, bh1);
                    mma_tf32(acc[m][t], al[m], bh0, bh1);
                    mma_tf32(acc[m][t], ah[m], bl0, bl1);
                }
            }
        }
        __syncthreads();
    }

    // epilogue: scale rows by rsqrt(indeg+1), store float2 pairs
#pragma unroll
    for (int m = 0; m < 2; ++m) {
        int rA = row0 + wrow + m * 16 + gid;
        int rB = rA + 8;
        if (rA < N_NODES) {
            float dA = rsqrtf((float)g_cnt[rA] + 1.f);
#pragma unroll
            for (int t = 0; t < 4; ++t) {
                int col = t * 8 + tig * 2;
                *(float2*)(g_xw + rA * 32 + col) =
                    make_float2(acc[m][t][0] * dA, acc[m][t][1] * dA);
            }
        }
        if (rB < N_NODES) {
            float dB = rsqrtf((float)g_cnt[rB] + 1.f);
#pragma unroll
            for (int t = 0; t < 4; ++t) {
                int col = t * 8 + tig * 2;
                *(float2*)(g_xw + rB * 32 + col) =
                    make_float2(acc[m][t][2] * dB, acc[m][t][3] * dB);
            }
        }
    }
}

// ---------------- 5) CSR fill (2 edges / thread, batched loads) --------------
__global__ void fill_kernel(const int* __restrict__ eidx) {
    int t = blockIdx.x * blockDim.x + threadIdx.x;
    if (t >= N_EDGES / 2) return;
    int2 r = *(const int2*)(eidx + t * 2);
    int2 c = *(const int2*)(eidx + N_EDGES + t * 2);
    int pos0 = atomicAdd(&g_cursor[c.x], 1);
    int pos1 = atomicAdd(&g_cursor[c.y], 1);
    g_src[pos0] = r.x;
    g_src[pos1] = r.y;
}

// ---------------- 6) conv0 + fused (hw, u, v) --------------------------------
__global__ __launch_bounds__(256) void conv0_kernel(const float* __restrict__ b0,
                                                    const float* __restrict__ W1) {
    __shared__ float hsm[8][32];
    int warp = (blockIdx.x * blockDim.x + threadIdx.x) >> 5;
    int lane = threadIdx.x & 31;
    int w = threadIdx.x >> 5;
    if (warp >= N_NODES) return;
    int node = warp;
    int s = g_off[node];
    int e = s + g_cnt[node];
    int g = lane >> 3;
    int f4 = (lane & 7) * 4;

    float4 acc;
    if (g == 0) acc = *(const float4*)(g_xw + node * 32 + f4);  // self (pre-scaled)
    else        acc = make_float4(0.f, 0.f, 0.f, 0.f);

    for (int p0 = s; p0 < e; p0 += 8) {
        int pA = p0 + g;
        int pB = p0 + 4 + g;
        int rA = (pA < e) ? g_src[pA] : -1;
        int rB = (pB < e) ? g_src[pB] : -1;
        if (rA >= 0) {
            float4 xv = *(const float4*)(g_xw + rA * 32 + f4);
            acc.x += xv.x; acc.y += xv.y; acc.z += xv.z; acc.w += xv.w;
        }
        if (rB >= 0) {
            float4 xv = *(const float4*)(g_xw + rB * 32 + f4);
            acc.x += xv.x; acc.y += xv.y; acc.z += xv.z; acc.w += xv.w;
        }
    }
    acc.x += __shfl_xor_sync(0xffffffffu, acc.x, 8);
    acc.y += __shfl_xor_sync(0xffffffffu, acc.y, 8);
    acc.z += __shfl_xor_sync(0xffffffffu, acc.z, 8);
    acc.w += __shfl_xor_sync(0xffffffffu, acc.w, 8);
    acc.x += __shfl_xor_sync(0xffffffffu, acc.x, 16);
    acc.y += __shfl_xor_sync(0xffffffffu, acc.y, 16);
    acc.z += __shfl_xor_sync(0xffffffffu, acc.z, 16);
    acc.w += __shfl_xor_sync(0xffffffffu, acc.w, 16);

    float dc = g_dinv0[node];
    if (g == 0) {
        hsm[w][f4 + 0] = dc * acc.x + __ldg(b0 + f4 + 0);
        hsm[w][f4 + 1] = dc * acc.y + __ldg(b0 + f4 + 1);
        hsm[w][f4 + 2] = dc * acc.z + __ldg(b0 + f4 + 2);
        hsm[w][f4 + 3] = dc * acc.w + __ldg(b0 + f4 + 3);
    }
    __syncwarp();

    float q = 0.f;
    if (lane < 8) {
#pragma unroll
        for (int j = 0; j < 32; ++j) q += hsm[w][j] * __ldg(W1 + j * 8 + lane);
        g_hw[node * 8 + lane] = q;
    } else if (lane == 8) {
#pragma unroll
        for (int j = 0; j < 32; ++j) q += hsm[w][j] * g_att_a[j];
        g_u[node] = q;
    } else if (lane == 9) {
#pragma unroll
        for (int j = 0; j < 32; ++j) q += hsm[w][j] * g_att_b[j];
        g_v[node] = q;
    }
}

// ---------------- 7) attention weights + dinv1 + hws -------------------------
__global__ __launch_bounds__(256) void attn_kernel() {
    int warp = (blockIdx.x * blockDim.x + threadIdx.x) >> 5;
    int lane = threadIdx.x & 31;
    if (warp >= N_NODES) return;
    int node = warp;
    float vc = g_v[node] + g_cst;
    int s = g_off[node];
    int e = s + g_cnt[node];
    float sum = 0.f;
    for (int p0 = s; p0 < e; p0 += 32) {
        int p = p0 + lane;
        float mw = 0.f;
        if (p < e) {
            int r = g_src[p];
            float wgt = fmaxf(g_u[r] + vc, 0.f);
            float m = fminf(ZETA / (1.f + __expf(-wgt)), 1.f);
            mw = m * wgt;
            g_mw[p] = mw;
        }
        sum += mw;
    }
    sum = wred(sum);
    float d1 = rsqrtf(sum + 1.0f);
    if (lane == 0) g_dinv1[node] = d1;
    if (lane < 8) g_hws[node * 8 + lane] = d1 * g_hw[node * 8 + lane];
}

// ---------------- 8) conv1 ---------------------------------------------------
__global__ __launch_bounds__(256) void conv1_kernel(const float* __restrict__ b1,
                                                    float* __restrict__ out) {
    int warp = (blockIdx.x * blockDim.x + threadIdx.x) >> 5;
    int lane = threadIdx.x & 31;
    if (warp >= N_NODES) return;
    int node = warp;
    int s = g_off[node];
    int e = s + g_cnt[node];
    int g = lane >> 3;
    int f = lane & 7;

    float acc = (g == 0) ? g_hws[node * 8 + f] : 0.f;  // self term

    for (int p0 = s; p0 < e; p0 += 8) {
        int pA = p0 + g;
        int pB = p0 + 4 + g;
        int rA = (pA < e) ? g_src[pA] : -1;
        int rB = (pB < e) ? g_src[pB] : -1;
        float cA = (pA < e) ? g_mw[pA] : 0.f;
        float cB = (pB < e) ? g_mw[pB] : 0.f;
        if (rA >= 0) acc += cA * g_hws[rA * 8 + f];
        if (rB >= 0) acc += cB * g_hws[rB * 8 + f];
    }
    acc += __shfl_xor_sync(0xffffffffu, acc, 8);
    acc += __shfl_xor_sync(0xffffffffu, acc, 16);

    if (lane < 8)
        out[node * 8 + lane] = g_dinv1[node] * acc + __ldg(b1 + lane);
}

// ---------------- launch -----------------------------------------------------
extern "C" void kernel_launch(void* const* d_in, const int* in_sizes, int n_in,
                              void* d_out, int out_size) {
    const float* x     = (const float*)d_in[0];
    const int*   eidx  = (const int*)  d_in[1];
    const float* W0    = (const float*)d_in[2];
    const float* b0    = (const float*)d_in[3];
    const float* W1    = (const float*)d_in[4];
    const float* b1    = (const float*)d_in[5];
    const float* Wnb   = (const float*)d_in[6];
    const float* bnb   = (const float*)d_in[7];
    const float* Wself = (const float*)d_in[8];
    const float* bself = (const float*)d_in[9];
    const float* Watt  = (const float*)d_in[10];
    const float* batt  = (const float*)d_in[11];
    float* out = (float*)d_out;

    zero_prep<<<NB_SCAN, 1024>>>(W0, Wnb, bnb, Wself, bself, Watt, batt);     // 0
    count_kernel<<<(N_EDGES / 4 + 255) / 256, 256>>>(eidx);                   // 1
    scan_fused<<<NB_SCAN, 1024>>>();                                          // 2
    gemm_xw<<<(N_NODES + 127) / 128, 128>>>(x);                               // 3 (profiled)
    fill_kernel<<<(N_EDGES / 2 + 255) / 256, 256>>>(eidx);                    // 4
    conv0_kernel<<<(N_NODES * 32 + 255) / 256, 256>>>(b0, W1);                // 5
    attn_kernel<<<(N_NODES * 32 + 255) / 256, 256>>>();                       // 6
    conv1_kernel<<<(N_NODES * 32 + 255) / 256, 256>>>(b1, out);               // 7
}